// round 11
// baseline (speedup 1.0000x reference)
#include <cuda_runtime.h>

// SheafLoss: B=4 T=1024 P=16 D=64 R=32 K=64, TAU=1
// d_in[0]=m (B,T,P,D) f32, d_in[1]=w (B,T,P) f32,
// d_in[2]=p (B,T,P,K) f32, d_in[3]=patch_centers (R,D) f32
// out: scalar f32

#define BT    4096
#define P_    16
#define D_    64
#define R_    32
#define K_    64
#define TPC   2
#define LN2   0.6931471805599453f

__device__ double g_acc;
__device__ unsigned int g_done;
__device__ float  g_omega[R_ * R_];
__device__ float  g_cn[R_];
__device__ float  g_hs[R_];     // hs[r] = sum_{s != r} omega[r][s]

__device__ __forceinline__ void cp_async16(unsigned saddr, const void* gaddr) {
    asm volatile("cp.async.ca.shared.global [%0], [%1], 16;" :: "r"(saddr), "l"(gaddr));
}
__device__ __forceinline__ void cp_commit() {
    asm volatile("cp.async.commit_group;");
}

// ---------------------------------------------------------------------------
// Setup: 4 blocks x 256 threads; block b handles rows [8b, 8b+8).
// ---------------------------------------------------------------------------
__global__ void __launch_bounds__(256) sheaf_setup_kernel(const float* __restrict__ gc) {
    __shared__ float sc[R_][D_ + 1];
    const int tid = threadIdx.x;
    for (int i = tid; i < R_ * D_; i += 256) sc[i >> 6][i & 63] = gc[i];
    __syncthreads();
    const int r = blockIdx.x * 8 + (tid >> 5);
    const int s = tid & 31;
    float cd = 0.f;
#pragma unroll 8
    for (int d = 0; d < D_; d++) {
        float df = sc[r][d] - sc[s][d];
        cd = fmaf(df, df, cd);
    }
    float omv = expf(-cd);
    g_omega[r * R_ + s] = omv;
    float hs = omv;
#pragma unroll
    for (int off = 16; off; off >>= 1)
        hs += __shfl_xor_sync(0xffffffffu, hs, off);
    if (s == 0) g_hs[r] = hs - 1.0f;
    float t = sc[r][s] * sc[r][s] + sc[r][s + 32] * sc[r][s + 32];
#pragma unroll
    for (int off = 16; off; off >>= 1)
        t += __shfl_xor_sync(0xffffffffu, t, off);
    if (s == 1) g_cn[r] = t;
    if (r == 0 && s == 2) { g_acc = 0.0; g_done = 0u; }
}

// ---------------------------------------------------------------------------
// Fully-unrolled pair segments for warp W. Rows {W, 15-W, 16+W, 31-W} sorted
// ascending for W in 0..7. All s constexpr -> immediate LDS offsets + shfl.
// ---------------------------------------------------------------------------
template<int W>
__device__ __forceinline__ void pair_loop(
    int lane, const float2 (*s_pb)[R_],
    float om0, float om1, float om2, float om3,
    const float pr2x[4], const float pr2y[4], float& lacc)
{
    constexpr int r0 = W, r1 = 15 - W, r2 = 16 + W, r3 = 31 - W;
#pragma unroll
    for (int s = r0 + 1; s <= r1; s++) {
        float2 ps = s_pb[s][lane];
        float m0 = fmaf(0.5f, ps.x, pr2x[0]);
        float m1 = fmaf(0.5f, ps.y, pr2y[0]);
        float tt = fmaf(m0, __log2f(m0), m1 * __log2f(m1));
        lacc = fmaf(__shfl_sync(0xffffffffu, om0, s), tt, lacc);
    }
#pragma unroll
    for (int s = r1 + 1; s <= r2; s++) {
        float2 ps = s_pb[s][lane];
        float m0 = fmaf(0.5f, ps.x, pr2x[0]);
        float m1 = fmaf(0.5f, ps.y, pr2y[0]);
        float tt = fmaf(m0, __log2f(m0), m1 * __log2f(m1));
        lacc = fmaf(__shfl_sync(0xffffffffu, om0, s), tt, lacc);
        m0 = fmaf(0.5f, ps.x, pr2x[1]);
        m1 = fmaf(0.5f, ps.y, pr2y[1]);
        tt = fmaf(m0, __log2f(m0), m1 * __log2f(m1));
        lacc = fmaf(__shfl_sync(0xffffffffu, om1, s), tt, lacc);
    }
#pragma unroll
    for (int s = r2 + 1; s <= r3; s++) {
        float2 ps = s_pb[s][lane];
        float m0 = fmaf(0.5f, ps.x, pr2x[0]);
        float m1 = fmaf(0.5f, ps.y, pr2y[0]);
        float tt = fmaf(m0, __log2f(m0), m1 * __log2f(m1));
        lacc = fmaf(__shfl_sync(0xffffffffu, om0, s), tt, lacc);
        m0 = fmaf(0.5f, ps.x, pr2x[1]);
        m1 = fmaf(0.5f, ps.y, pr2y[1]);
        tt = fmaf(m0, __log2f(m0), m1 * __log2f(m1));
        lacc = fmaf(__shfl_sync(0xffffffffu, om1, s), tt, lacc);
        m0 = fmaf(0.5f, ps.x, pr2x[2]);
        m1 = fmaf(0.5f, ps.y, pr2y[2]);
        tt = fmaf(m0, __log2f(m0), m1 * __log2f(m1));
        lacc = fmaf(__shfl_sync(0xffffffffu, om2, s), tt, lacc);
    }
#pragma unroll
    for (int s = r3 + 1; s < R_; s++) {
        float2 ps = s_pb[s][lane];
        float m0 = fmaf(0.5f, ps.x, pr2x[0]);
        float m1 = fmaf(0.5f, ps.y, pr2y[0]);
        float tt = fmaf(m0, __log2f(m0), m1 * __log2f(m1));
        lacc = fmaf(__shfl_sync(0xffffffffu, om0, s), tt, lacc);
        m0 = fmaf(0.5f, ps.x, pr2x[1]);
        m1 = fmaf(0.5f, ps.y, pr2y[1]);
        tt = fmaf(m0, __log2f(m0), m1 * __log2f(m1));
        lacc = fmaf(__shfl_sync(0xffffffffu, om1, s), tt, lacc);
        m0 = fmaf(0.5f, ps.x, pr2x[2]);
        m1 = fmaf(0.5f, ps.y, pr2y[2]);
        tt = fmaf(m0, __log2f(m0), m1 * __log2f(m1));
        lacc = fmaf(__shfl_sync(0xffffffffu, om2, s), tt, lacc);
        m0 = fmaf(0.5f, ps.x, pr2x[3]);
        m1 = fmaf(0.5f, ps.y, pr2y[3]);
        tt = fmaf(m0, __log2f(m0), m1 * __log2f(m1));
        lacc = fmaf(__shfl_sync(0xffffffffu, om3, s), tt, lacc);
    }
}

// ---------------------------------------------------------------------------
// Main: one CTA per 2 tiles, 256 threads, 6 CTAs/SM (regs <= 42, no spills).
// t-loop forced rolled (code size); pair loop unrolled per warp.
// ---------------------------------------------------------------------------
__global__ void __launch_bounds__(256, 6) sheaf_kernel(
    const float* __restrict__ gm,
    const float* __restrict__ gw,
    const float* __restrict__ gp,
    const float* __restrict__ gc,
    float* __restrict__ gout)
{
    __shared__ float  s_c[R_][68];        // centers row-major, 16B rows
    __shared__ float4 s_m[2][256];        // double-buffered m tile
    __shared__ float4 s_p[256];           // single-buffered p tile
    __shared__ float  s_w[2][P_];
    __shared__ float  s_sm[P_][R_ + 1];
    __shared__ float2 s_pb[R_][R_];       // [r][lane] = (p_bar[2l], p_bar[2l+1])
    __shared__ float  s_cn[R_];
    __shared__ float  s_hs[R_];
    __shared__ float  s_red[8];

    const int tid  = threadIdx.x;
    const int lane = tid & 31;
    const int wid  = tid >> 5;
    const int bt0  = blockIdx.x * TPC;

    const int r0 = wid, r1 = 15 - wid, r2 = 16 + wid, r3 = 31 - wid;

    // per-CTA constants
    for (int i = tid; i < R_ * D_; i += 256) s_c[i >> 6][i & 63] = gc[i];
    if (tid < R_) { s_cn[tid] = g_cn[tid]; s_hs[tid] = g_hs[tid]; }

    // tile-invariant omega rows, register-resident
    const float om0 = g_omega[r0 * R_ + lane];
    const float om1 = g_omega[r1 * R_ + lane];
    const float om2 = g_omega[r2 * R_ + lane];
    const float om3 = g_omega[r3 * R_ + lane];

    // prologue: async-copy m0 + p0
    {
        unsigned a = (unsigned)__cvta_generic_to_shared(&s_m[0][tid]);
        unsigned b = (unsigned)__cvta_generic_to_shared(&s_p[tid]);
        cp_async16(a, (const float4*)(gm + (size_t)bt0 * 1024) + tid);
        cp_async16(b, (const float4*)(gp + (size_t)bt0 * 1024) + tid);
        cp_commit();
    }
    float pw = (tid < P_) ? gw[(size_t)bt0 * P_ + tid] : 0.f;

    float lacc = 0.f;   // per-lane, log2 domain
    float eacc = 0.f;   // lane-uniform per warp, log2 domain

#pragma unroll 1
    for (int t = 0; t < TPC; t++) {
        if (t + 1 < TPC) {
            unsigned a = (unsigned)__cvta_generic_to_shared(&s_m[t + 1][tid]);
            cp_async16(a, (const float4*)(gm + (size_t)(bt0 + t + 1) * 1024) + tid);
            cp_commit();
            asm volatile("cp.async.wait_group 1;");   // m(t), p(t) done
        } else {
            asm volatile("cp.async.wait_group 0;");   // all done
        }
        if (tid < P_) s_w[t][tid] = pw;
        __syncthreads();   // buffers visible; all warps done pair(t-1)
        if (t + 1 < TPC && tid < P_) pw = gw[(size_t)(bt0 + t + 1) * P_ + tid];

        const float* smt = (const float*)s_m[t];

        // ---- step 1: logits = 2*m.c - |c|^2 (no max-sub; |l| << 88) ----
        {
            const int p0 = wid, p1 = wid + 8;
            const int r = lane;
            float a0 = 0.f, a1 = 0.f;
#pragma unroll
            for (int d = 0; d < D_; d += 4) {
                float4 cv  = *(const float4*)&s_c[r][d];
                float4 mv0 = *(const float4*)&smt[p0 * D_ + d];
                float4 mv1 = *(const float4*)&smt[p1 * D_ + d];
                a0 = fmaf(mv0.x, cv.x, fmaf(mv0.y, cv.y, fmaf(mv0.z, cv.z, fmaf(mv0.w, cv.w, a0))));
                a1 = fmaf(mv1.x, cv.x, fmaf(mv1.y, cv.y, fmaf(mv1.z, cv.z, fmaf(mv1.w, cv.w, a1))));
            }
            const float cn = s_cn[r];
            float e0 = __expf(fmaf(2.f, a0, -cn));
            float e1 = __expf(fmaf(2.f, a1, -cn));
            float sm0 = e0, sm1 = e1;
#pragma unroll
            for (int off = 16; off; off >>= 1) {
                sm0 += __shfl_xor_sync(0xffffffffu, sm0, off);
                sm1 += __shfl_xor_sync(0xffffffffu, sm1, off);
            }
            s_sm[p0][lane] = e0 * (s_w[t][p0] / sm0);
            s_sm[p1][lane] = e1 * (s_w[t][p1] / sm1);
        }
        __syncthreads();

        // ---- step 3: p_bar + E_r; rows {r0..r3}; LDS.64 k-pairs ----
        float pr2x[4], pr2y[4];
        {
            const float* spt = (const float*)s_p;
            const int rows[4] = { r0, r1, r2, r3 };
            float acc0[4] = {0.f,0.f,0.f,0.f};
            float acc1[4] = {0.f,0.f,0.f,0.f};
#pragma unroll
            for (int pp = 0; pp < P_; pp++) {
                float2 sp = *(const float2*)&spt[pp * K_ + 2 * lane];
#pragma unroll
                for (int j = 0; j < 4; j++) {
                    float g = s_sm[pp][rows[j]];
                    acc0[j] = fmaf(sp.x, g, acc0[j]);
                    acc1[j] = fmaf(sp.y, g, acc1[j]);
                }
            }
#pragma unroll
            for (int j = 0; j < 4; j++) {
                const int r = rows[j];
                float v = (lane < P_) ? s_sm[lane][r] : 0.f;
#pragma unroll
                for (int off = 16; off; off >>= 1)
                    v += __shfl_xor_sync(0xffffffffu, v, off);
                float tm = 1.0f / (v + 1e-6f);
                float pb0 = acc0[j] * tm;
                float pb1 = acc1[j] * tm;
                s_pb[r][lane] = make_float2(pb0, pb1);
                pr2x[j] = fmaf(0.5f, pb0, 1e-8f);
                pr2y[j] = fmaf(0.5f, pb1, 1e-8f);
                float e = fmaf(pb0, __log2f(pb0 + 1e-8f), pb1 * __log2f(pb1 + 1e-8f));
#pragma unroll
                for (int off = 16; off; off >>= 1)
                    e += __shfl_xor_sync(0xffffffffu, e, off);
                eacc = fmaf(e, s_hs[r], eacc);
            }
        }
        __syncthreads();   // step3 done: s_p free for prefetch, s_pb ready

        // prefetch p(t+1), overlapped with pair loop
        if (t + 1 < TPC) {
            unsigned b = (unsigned)__cvta_generic_to_shared(&s_p[tid]);
            cp_async16(b, (const float4*)(gp + (size_t)(bt0 + t + 1) * 1024) + tid);
            cp_commit();
        }

        // ---- pair loop: fully unrolled per-warp variant ----
        switch (wid) {
            case 0: pair_loop<0>(lane, s_pb, om0, om1, om2, om3, pr2x, pr2y, lacc); break;
            case 1: pair_loop<1>(lane, s_pb, om0, om1, om2, om3, pr2x, pr2y, lacc); break;
            case 2: pair_loop<2>(lane, s_pb, om0, om1, om2, om3, pr2x, pr2y, lacc); break;
            case 3: pair_loop<3>(lane, s_pb, om0, om1, om2, om3, pr2x, pr2y, lacc); break;
            case 4: pair_loop<4>(lane, s_pb, om0, om1, om2, om3, pr2x, pr2y, lacc); break;
            case 5: pair_loop<5>(lane, s_pb, om0, om1, om2, om3, pr2x, pr2y, lacc); break;
            case 6: pair_loop<6>(lane, s_pb, om0, om1, om2, om3, pr2x, pr2y, lacc); break;
            case 7: pair_loop<7>(lane, s_pb, om0, om1, om2, om3, pr2x, pr2y, lacc); break;
        }
    }

    // ---- final reduction + last-CTA writeout (log2 domain, scale once) ----
#pragma unroll
    for (int off = 16; off; off >>= 1)
        lacc += __shfl_xor_sync(0xffffffffu, lacc, off);
    if (lane == 0) s_red[wid] = fmaf(0.5f, eacc, -lacc) * LN2;
    __syncthreads();
    if (tid == 0) {
        float a = 0.f;
#pragma unroll
        for (int i = 0; i < 8; i++) a += s_red[i];
        atomicAdd(&g_acc, (double)a);
        __threadfence();
        unsigned int ticket = atomicAdd(&g_done, 1u);
        if (ticket == gridDim.x - 1) {
            double total = *(volatile double*)&g_acc;
            gout[0] = (float)(total / (496.0 + 1e-8));
        }
    }
}

extern "C" void kernel_launch(void* const* d_in, const int* in_sizes, int n_in,
                              void* d_out, int out_size) {
    const float* m = (const float*)d_in[0];
    const float* w = (const float*)d_in[1];
    const float* p = (const float*)d_in[2];
    const float* c = (const float*)d_in[3];
    float* out = (float*)d_out;
    (void)in_sizes; (void)n_in; (void)out_size;

    sheaf_setup_kernel<<<4, 256>>>(c);
    sheaf_kernel<<<BT / TPC, 256>>>(m, w, p, c, out);
}

// round 12
// speedup vs baseline: 2.0338x; 2.0338x over previous
#include <cuda_runtime.h>

// SheafLoss: B=4 T=1024 P=16 D=64 R=32 K=64, TAU=1
// d_in[0]=m (B,T,P,D) f32, d_in[1]=w (B,T,P) f32,
// d_in[2]=p (B,T,P,K) f32, d_in[3]=patch_centers (R,D) f32
// out: scalar f32

#define BT    4096
#define P_    16
#define D_    64
#define R_    32
#define K_    64
#define TPC   2
#define LN2   0.6931471805599453f

__device__ double g_acc;
__device__ unsigned int g_done;
__device__ float  g_omega[R_ * R_];
__device__ float  g_cn[R_];
__device__ float  g_hs[R_];     // hs[r] = sum_{s != r} omega[r][s]

__device__ __forceinline__ void cp_async16(unsigned saddr, const void* gaddr) {
    asm volatile("cp.async.ca.shared.global [%0], [%1], 16;" :: "r"(saddr), "l"(gaddr));
}
__device__ __forceinline__ void cp_commit() {
    asm volatile("cp.async.commit_group;");
}

// ---------------------------------------------------------------------------
// Setup: 4 blocks x 256 threads; block b handles rows [8b, 8b+8).
// ---------------------------------------------------------------------------
__global__ void __launch_bounds__(256) sheaf_setup_kernel(const float* __restrict__ gc) {
    __shared__ float sc[R_][D_ + 1];
    const int tid = threadIdx.x;
    for (int i = tid; i < R_ * D_; i += 256) sc[i >> 6][i & 63] = gc[i];
    __syncthreads();
    const int r = blockIdx.x * 8 + (tid >> 5);
    const int s = tid & 31;
    float cd = 0.f;
#pragma unroll 8
    for (int d = 0; d < D_; d++) {
        float df = sc[r][d] - sc[s][d];
        cd = fmaf(df, df, cd);
    }
    float omv = expf(-cd);
    g_omega[r * R_ + s] = omv;
    float hs = omv;
#pragma unroll
    for (int off = 16; off; off >>= 1)
        hs += __shfl_xor_sync(0xffffffffu, hs, off);
    if (s == 0) g_hs[r] = hs - 1.0f;
    float t = sc[r][s] * sc[r][s] + sc[r][s + 32] * sc[r][s + 32];
#pragma unroll
    for (int off = 16; off; off >>= 1)
        t += __shfl_xor_sync(0xffffffffu, t, off);
    if (s == 1) g_cn[r] = t;
    if (r == 0 && s == 2) { g_acc = 0.0; g_done = 0u; }
}

// ---------------------------------------------------------------------------
// Main: one CTA per 2 tiles, 256 threads, 6 CTAs/SM. Compact rolled code
// (R9 envelope). Lane owns k-slice (2*lane, 2*lane+1); warp row set
// {w, 15-w, 16+w, 31-w} (sorted ascending); omega rows in registers via shfl.
// ---------------------------------------------------------------------------
__global__ void __launch_bounds__(256, 6) sheaf_kernel(
    const float* __restrict__ gm,
    const float* __restrict__ gw,
    const float* __restrict__ gp,
    const float* __restrict__ gc,
    float* __restrict__ gout)
{
    __shared__ float  s_c[R_][68];        // centers row-major, 16B rows
    __shared__ float4 s_m[2][256];        // double-buffered m tile
    __shared__ float4 s_p[2][256];        // double-buffered p tile
    __shared__ float  s_w[2][P_];
    __shared__ float  s_sm[P_][R_ + 1];
    __shared__ float2 s_pb[R_][R_];       // [r][lane] = (p_bar[2l], p_bar[2l+1])
    __shared__ float  s_cn[R_];
    __shared__ float  s_hs[R_];
    __shared__ float  s_red[8];

    const int tid  = threadIdx.x;
    const int lane = tid & 31;
    const int wid  = tid >> 5;
    const int bt0  = blockIdx.x * TPC;

    const int r0 = wid, r1 = 15 - wid, r2 = 16 + wid, r3 = 31 - wid;

    // per-CTA constants
    for (int i = tid; i < R_ * D_; i += 256) s_c[i >> 6][i & 63] = gc[i];
    if (tid < R_) { s_cn[tid] = g_cn[tid]; s_hs[tid] = g_hs[tid]; }

    // tile-invariant omega rows, register-resident
    const float om0 = g_omega[r0 * R_ + lane];
    const float om1 = g_omega[r1 * R_ + lane];
    const float om2 = g_omega[r2 * R_ + lane];
    const float om3 = g_omega[r3 * R_ + lane];

    // prologue: async-copy tile 0
    {
        unsigned a = (unsigned)__cvta_generic_to_shared(&s_m[0][tid]);
        unsigned b = (unsigned)__cvta_generic_to_shared(&s_p[0][tid]);
        cp_async16(a, (const float4*)(gm + (size_t)bt0 * 1024) + tid);
        cp_async16(b, (const float4*)(gp + (size_t)bt0 * 1024) + tid);
        cp_commit();
    }
    float pw = (tid < P_) ? gw[(size_t)bt0 * P_ + tid] : 0.f;

    float lacc = 0.f;   // per-lane, log2 domain
    float eacc = 0.f;   // lane-uniform per warp, log2 domain

#pragma unroll 1
    for (int t = 0; t < TPC; t++) {
        if (t + 1 < TPC) {
            const int bt1 = bt0 + t + 1;
            unsigned a = (unsigned)__cvta_generic_to_shared(&s_m[t + 1][tid]);
            unsigned b = (unsigned)__cvta_generic_to_shared(&s_p[t + 1][tid]);
            cp_async16(a, (const float4*)(gm + (size_t)bt1 * 1024) + tid);
            cp_async16(b, (const float4*)(gp + (size_t)bt1 * 1024) + tid);
            cp_commit();
            asm volatile("cp.async.wait_group 1;");
        } else {
            asm volatile("cp.async.wait_group 0;");
        }
        if (tid < P_) s_w[t][tid] = pw;
        __syncthreads();   // buf t visible; all warps done with pair(t-1)
        if (t + 1 < TPC && tid < P_) pw = gw[(size_t)(bt0 + t + 1) * P_ + tid];

        const float* smt = (const float*)s_m[t];
        const float* spt = (const float*)s_p[t];

        // ---- step 1: logits = 2*m.c - |c|^2; no max-sub (validated) ----
        {
            const int p0 = wid, p1 = wid + 8;
            const int r = lane;
            float a0 = 0.f, a1 = 0.f;
#pragma unroll
            for (int d = 0; d < D_; d += 4) {
                float4 cv  = *(const float4*)&s_c[r][d];
                float4 mv0 = *(const float4*)&smt[p0 * D_ + d];
                float4 mv1 = *(const float4*)&smt[p1 * D_ + d];
                a0 = fmaf(mv0.x, cv.x, fmaf(mv0.y, cv.y, fmaf(mv0.z, cv.z, fmaf(mv0.w, cv.w, a0))));
                a1 = fmaf(mv1.x, cv.x, fmaf(mv1.y, cv.y, fmaf(mv1.z, cv.z, fmaf(mv1.w, cv.w, a1))));
            }
            const float cn = s_cn[r];
            float e0 = __expf(fmaf(2.f, a0, -cn));
            float e1 = __expf(fmaf(2.f, a1, -cn));
            float sm0 = e0, sm1 = e1;
#pragma unroll
            for (int off = 16; off; off >>= 1) {
                sm0 += __shfl_xor_sync(0xffffffffu, sm0, off);
                sm1 += __shfl_xor_sync(0xffffffffu, sm1, off);
            }
            s_sm[p0][lane] = e0 * (s_w[t][p0] / sm0);
            s_sm[p1][lane] = e1 * (s_w[t][p1] / sm1);
        }
        __syncthreads();

        // ---- step 3: p_bar + E_r; rows {r0..r3}; LDS.64 k-pairs ----
        float pr2x[4], pr2y[4];
        {
            const int rows[4] = { r0, r1, r2, r3 };
            float acc0[4] = {0.f,0.f,0.f,0.f};
            float acc1[4] = {0.f,0.f,0.f,0.f};
#pragma unroll
            for (int pp = 0; pp < P_; pp++) {
                float2 sp = *(const float2*)&spt[pp * K_ + 2 * lane];
#pragma unroll
                for (int j = 0; j < 4; j++) {
                    float g = s_sm[pp][rows[j]];
                    acc0[j] = fmaf(sp.x, g, acc0[j]);
                    acc1[j] = fmaf(sp.y, g, acc1[j]);
                }
            }
#pragma unroll
            for (int j = 0; j < 4; j++) {
                const int r = rows[j];
                float v = (lane < P_) ? s_sm[lane][r] : 0.f;
#pragma unroll
                for (int off = 16; off; off >>= 1)
                    v += __shfl_xor_sync(0xffffffffu, v, off);
                float tm = 1.0f / (v + 1e-6f);
                float pb0 = acc0[j] * tm;
                float pb1 = acc1[j] * tm;
                s_pb[r][lane] = make_float2(pb0, pb1);
                pr2x[j] = fmaf(0.5f, pb0, 1e-8f);
                pr2y[j] = fmaf(0.5f, pb1, 1e-8f);
                float e = fmaf(pb0, __log2f(pb0 + 1e-8f), pb1 * __log2f(pb1 + 1e-8f));
#pragma unroll
                for (int off = 16; off; off >>= 1)
                    e += __shfl_xor_sync(0xffffffffu, e, off);
                eacc = fmaf(e, s_hs[r], eacc);
            }
        }
        __syncthreads();

        // ---- pair loop: 4 rolled branch-free segments; ps loaded once per s;
        //      omega from registers via shfl. Compact code (I$-friendly). ----
        {
            for (int s = r0 + 1; s <= r1; s++) {
                float2 ps = s_pb[s][lane];
                float m0 = fmaf(0.5f, ps.x, pr2x[0]);
                float m1 = fmaf(0.5f, ps.y, pr2y[0]);
                float tt = fmaf(m0, __log2f(m0), m1 * __log2f(m1));
                lacc = fmaf(__shfl_sync(0xffffffffu, om0, s), tt, lacc);
            }
            for (int s = r1 + 1; s <= r2; s++) {
                float2 ps = s_pb[s][lane];
                float m0 = fmaf(0.5f, ps.x, pr2x[0]);
                float m1 = fmaf(0.5f, ps.y, pr2y[0]);
                float tt = fmaf(m0, __log2f(m0), m1 * __log2f(m1));
                lacc = fmaf(__shfl_sync(0xffffffffu, om0, s), tt, lacc);
                m0 = fmaf(0.5f, ps.x, pr2x[1]);
                m1 = fmaf(0.5f, ps.y, pr2y[1]);
                tt = fmaf(m0, __log2f(m0), m1 * __log2f(m1));
                lacc = fmaf(__shfl_sync(0xffffffffu, om1, s), tt, lacc);
            }
            for (int s = r2 + 1; s <= r3; s++) {
                float2 ps = s_pb[s][lane];
                float m0 = fmaf(0.5f, ps.x, pr2x[0]);
                float m1 = fmaf(0.5f, ps.y, pr2y[0]);
                float tt = fmaf(m0, __log2f(m0), m1 * __log2f(m1));
                lacc = fmaf(__shfl_sync(0xffffffffu, om0, s), tt, lacc);
                m0 = fmaf(0.5f, ps.x, pr2x[1]);
                m1 = fmaf(0.5f, ps.y, pr2y[1]);
                tt = fmaf(m0, __log2f(m0), m1 * __log2f(m1));
                lacc = fmaf(__shfl_sync(0xffffffffu, om1, s), tt, lacc);
                m0 = fmaf(0.5f, ps.x, pr2x[2]);
                m1 = fmaf(0.5f, ps.y, pr2y[2]);
                tt = fmaf(m0, __log2f(m0), m1 * __log2f(m1));
                lacc = fmaf(__shfl_sync(0xffffffffu, om2, s), tt, lacc);
            }
            for (int s = r3 + 1; s < R_; s++) {
                float2 ps = s_pb[s][lane];
                float m0 = fmaf(0.5f, ps.x, pr2x[0]);
                float m1 = fmaf(0.5f, ps.y, pr2y[0]);
                float tt = fmaf(m0, __log2f(m0), m1 * __log2f(m1));
                lacc = fmaf(__shfl_sync(0xffffffffu, om0, s), tt, lacc);
                m0 = fmaf(0.5f, ps.x, pr2x[1]);
                m1 = fmaf(0.5f, ps.y, pr2y[1]);
                tt = fmaf(m0, __log2f(m0), m1 * __log2f(m1));
                lacc = fmaf(__shfl_sync(0xffffffffu, om1, s), tt, lacc);
                m0 = fmaf(0.5f, ps.x, pr2x[2]);
                m1 = fmaf(0.5f, ps.y, pr2y[2]);
                tt = fmaf(m0, __log2f(m0), m1 * __log2f(m1));
                lacc = fmaf(__shfl_sync(0xffffffffu, om2, s), tt, lacc);
                m0 = fmaf(0.5f, ps.x, pr2x[3]);
                m1 = fmaf(0.5f, ps.y, pr2y[3]);
                tt = fmaf(m0, __log2f(m0), m1 * __log2f(m1));
                lacc = fmaf(__shfl_sync(0xffffffffu, om3, s), tt, lacc);
            }
        }
    }

    // ---- final reduction + last-CTA writeout (log2 domain, scale once) ----
#pragma unroll
    for (int off = 16; off; off >>= 1)
        lacc += __shfl_xor_sync(0xffffffffu, lacc, off);
    if (lane == 0) s_red[wid] = fmaf(0.5f, eacc, -lacc) * LN2;
    __syncthreads();
    if (tid == 0) {
        float a = 0.f;
#pragma unroll
        for (int i = 0; i < 8; i++) a += s_red[i];
        atomicAdd(&g_acc, (double)a);
        __threadfence();
        unsigned int ticket = atomicAdd(&g_done, 1u);
        if (ticket == gridDim.x - 1) {
            double total = *(volatile double*)&g_acc;
            gout[0] = (float)(total / (496.0 + 1e-8));
        }
    }
}

extern "C" void kernel_launch(void* const* d_in, const int* in_sizes, int n_in,
                              void* d_out, int out_size) {
    const float* m = (const float*)d_in[0];
    const float* w = (const float*)d_in[1];
    const float* p = (const float*)d_in[2];
    const float* c = (const float*)d_in[3];
    float* out = (float*)d_out;
    (void)in_sizes; (void)n_in; (void)out_size;

    sheaf_setup_kernel<<<4, 256>>>(c);
    sheaf_kernel<<<BT / TPC, 256>>>(m, w, p, c, out);
}

// round 13
// speedup vs baseline: 2.0539x; 1.0099x over previous
#include <cuda_runtime.h>

// SheafLoss: B=4 T=1024 P=16 D=64 R=32 K=64, TAU=1
// d_in[0]=m (B,T,P,D) f32, d_in[1]=w (B,T,P) f32,
// d_in[2]=p (B,T,P,K) f32, d_in[3]=patch_centers (R,D) f32
// out: scalar f32

#define BT    4096
#define P_    16
#define D_    64
#define R_    32
#define K_    64
#define GRID_ 912          // 152 SMs x 6 CTAs: one persistent wave
#define LN2   0.6931471805599453f

__device__ double g_acc;
__device__ unsigned int g_done;
__device__ float  g_omega[R_ * R_];
__device__ float  g_cn[R_];
__device__ float  g_hs[R_];     // hs[r] = sum_{s != r} omega[r][s]

__device__ __forceinline__ void cp_async16(unsigned saddr, const void* gaddr) {
    asm volatile("cp.async.ca.shared.global [%0], [%1], 16;" :: "r"(saddr), "l"(gaddr));
}
__device__ __forceinline__ void cp_commit() {
    asm volatile("cp.async.commit_group;");
}

// ---------------------------------------------------------------------------
// Setup: 4 blocks x 256 threads; block b handles rows [8b, 8b+8).
// ---------------------------------------------------------------------------
__global__ void __launch_bounds__(256) sheaf_setup_kernel(const float* __restrict__ gc) {
    __shared__ float sc[R_][D_ + 1];
    const int tid = threadIdx.x;
    for (int i = tid; i < R_ * D_; i += 256) sc[i >> 6][i & 63] = gc[i];
    __syncthreads();
    const int r = blockIdx.x * 8 + (tid >> 5);
    const int s = tid & 31;
    float cd = 0.f;
#pragma unroll 8
    for (int d = 0; d < D_; d++) {
        float df = sc[r][d] - sc[s][d];
        cd = fmaf(df, df, cd);
    }
    float omv = expf(-cd);
    g_omega[r * R_ + s] = omv;
    float hs = omv;
#pragma unroll
    for (int off = 16; off; off >>= 1)
        hs += __shfl_xor_sync(0xffffffffu, hs, off);
    if (s == 0) g_hs[r] = hs - 1.0f;
    float t = sc[r][s] * sc[r][s] + sc[r][s + 32] * sc[r][s + 32];
#pragma unroll
    for (int off = 16; off; off >>= 1)
        t += __shfl_xor_sync(0xffffffffu, t, off);
    if (s == 1) g_cn[r] = t;
    if (r == 0 && s == 2) { g_acc = 0.0; g_done = 0u; }
}

// ---------------------------------------------------------------------------
// Main: persistent grid (912 CTAs), grid-stride over tiles, 256 threads,
// 6 CTAs/SM. Double-buffered m/p keyed by iteration parity. Compact rolled
// code (R12 envelope). Lane owns k-slice (2*lane, 2*lane+1); warp row set
// {w, 15-w, 16+w, 31-w}; omega rows register-resident via shfl.
// ---------------------------------------------------------------------------
__global__ void __launch_bounds__(256, 6) sheaf_kernel(
    const float* __restrict__ gm,
    const float* __restrict__ gw,
    const float* __restrict__ gp,
    const float* __restrict__ gc,
    float* __restrict__ gout)
{
    __shared__ float  s_c[R_][68];        // centers row-major, 16B rows
    __shared__ float4 s_m[2][256];        // double-buffered m tile
    __shared__ float4 s_p[2][256];        // double-buffered p tile
    __shared__ float  s_w[2][P_];
    __shared__ float  s_sm[P_][R_ + 1];
    __shared__ float2 s_pb[R_][R_];       // [r][lane] = (p_bar[2l], p_bar[2l+1])
    __shared__ float  s_cn[R_];
    __shared__ float  s_hs[R_];
    __shared__ float  s_red[8];

    const int tid  = threadIdx.x;
    const int lane = tid & 31;
    const int wid  = tid >> 5;

    const int r0 = wid, r1 = 15 - wid, r2 = 16 + wid, r3 = 31 - wid;

    // per-CTA constants (amortized over ~4.5 tiles)
    for (int i = tid; i < R_ * D_; i += 256) s_c[i >> 6][i & 63] = gc[i];
    if (tid < R_) { s_cn[tid] = g_cn[tid]; s_hs[tid] = g_hs[tid]; }

    // tile-invariant omega rows, register-resident
    const float om0 = g_omega[r0 * R_ + lane];
    const float om1 = g_omega[r1 * R_ + lane];
    const float om2 = g_omega[r2 * R_ + lane];
    const float om3 = g_omega[r3 * R_ + lane];

    // prologue: async-copy first tile into buffer 0
    {
        const int bt = blockIdx.x;
        unsigned a = (unsigned)__cvta_generic_to_shared(&s_m[0][tid]);
        unsigned b = (unsigned)__cvta_generic_to_shared(&s_p[0][tid]);
        cp_async16(a, (const float4*)(gm + (size_t)bt * 1024) + tid);
        cp_async16(b, (const float4*)(gp + (size_t)bt * 1024) + tid);
        cp_commit();
    }
    float pw = (tid < P_) ? gw[(size_t)blockIdx.x * P_ + tid] : 0.f;

    float lacc = 0.f;   // per-lane, log2 domain
    float eacc = 0.f;   // lane-uniform per warp, log2 domain

    int it = 0;
#pragma unroll 1
    for (int bt = blockIdx.x; bt < BT; bt += GRID_, it++) {
        const int buf = it & 1;
        const int btn = bt + GRID_;
        if (btn < BT) {
            // prefetch next tile into the other buffer (safe: last reads of
            // that buffer happened before iteration it-1's post-step3 barrier)
            unsigned a = (unsigned)__cvta_generic_to_shared(&s_m[buf ^ 1][tid]);
            unsigned b = (unsigned)__cvta_generic_to_shared(&s_p[buf ^ 1][tid]);
            cp_async16(a, (const float4*)(gm + (size_t)btn * 1024) + tid);
            cp_async16(b, (const float4*)(gp + (size_t)btn * 1024) + tid);
            cp_commit();
            asm volatile("cp.async.wait_group 1;");   // current tile resident
        } else {
            asm volatile("cp.async.wait_group 0;");
        }
        if (tid < P_) s_w[buf][tid] = pw;
        __syncthreads();   // buf visible; all warps done with previous pair loop
        if (btn < BT && tid < P_) pw = gw[(size_t)btn * P_ + tid];

        const float* smt = (const float*)s_m[buf];
        const float* spt = (const float*)s_p[buf];

        // ---- step 1: logits = 2*m.c - |c|^2; no max-sub (validated) ----
        {
            const int p0 = wid, p1 = wid + 8;
            const int r = lane;
            float a0 = 0.f, a1 = 0.f;
#pragma unroll
            for (int d = 0; d < D_; d += 4) {
                float4 cv  = *(const float4*)&s_c[r][d];
                float4 mv0 = *(const float4*)&smt[p0 * D_ + d];
                float4 mv1 = *(const float4*)&smt[p1 * D_ + d];
                a0 = fmaf(mv0.x, cv.x, fmaf(mv0.y, cv.y, fmaf(mv0.z, cv.z, fmaf(mv0.w, cv.w, a0))));
                a1 = fmaf(mv1.x, cv.x, fmaf(mv1.y, cv.y, fmaf(mv1.z, cv.z, fmaf(mv1.w, cv.w, a1))));
            }
            const float cn = s_cn[r];
            float e0 = __expf(fmaf(2.f, a0, -cn));
            float e1 = __expf(fmaf(2.f, a1, -cn));
            float sm0 = e0, sm1 = e1;
#pragma unroll
            for (int off = 16; off; off >>= 1) {
                sm0 += __shfl_xor_sync(0xffffffffu, sm0, off);
                sm1 += __shfl_xor_sync(0xffffffffu, sm1, off);
            }
            s_sm[p0][lane] = e0 * __fdividef(s_w[buf][p0], sm0);
            s_sm[p1][lane] = e1 * __fdividef(s_w[buf][p1], sm1);
        }
        __syncthreads();

        // ---- step 3: p_bar + E_r; rows {r0..r3}; LDS.64 k-pairs ----
        float pr2x[4], pr2y[4];
        {
            const int rows[4] = { r0, r1, r2, r3 };
            float acc0[4] = {0.f,0.f,0.f,0.f};
            float acc1[4] = {0.f,0.f,0.f,0.f};
#pragma unroll
            for (int pp = 0; pp < P_; pp++) {
                float2 sp = *(const float2*)&spt[pp * K_ + 2 * lane];
#pragma unroll
                for (int j = 0; j < 4; j++) {
                    float g = s_sm[pp][rows[j]];
                    acc0[j] = fmaf(sp.x, g, acc0[j]);
                    acc1[j] = fmaf(sp.y, g, acc1[j]);
                }
            }
#pragma unroll
            for (int j = 0; j < 4; j++) {
                const int r = rows[j];
                float v = (lane < P_) ? s_sm[lane][r] : 0.f;
#pragma unroll
                for (int off = 16; off; off >>= 1)
                    v += __shfl_xor_sync(0xffffffffu, v, off);
                float tm = __fdividef(1.0f, v + 1e-6f);
                float pb0 = acc0[j] * tm;
                float pb1 = acc1[j] * tm;
                s_pb[r][lane] = make_float2(pb0, pb1);
                pr2x[j] = fmaf(0.5f, pb0, 1e-8f);
                pr2y[j] = fmaf(0.5f, pb1, 1e-8f);
                float e = fmaf(pb0, __log2f(pb0 + 1e-8f), pb1 * __log2f(pb1 + 1e-8f));
#pragma unroll
                for (int off = 16; off; off >>= 1)
                    e += __shfl_xor_sync(0xffffffffu, e, off);
                eacc = fmaf(e, s_hs[r], eacc);
            }
        }
        __syncthreads();

        // ---- pair loop: 4 rolled branch-free segments; ps loaded once per s;
        //      omega from registers via shfl. Compact code (I$-friendly). ----
        {
            for (int s = r0 + 1; s <= r1; s++) {
                float2 ps = s_pb[s][lane];
                float m0 = fmaf(0.5f, ps.x, pr2x[0]);
                float m1 = fmaf(0.5f, ps.y, pr2y[0]);
                float tt = fmaf(m0, __log2f(m0), m1 * __log2f(m1));
                lacc = fmaf(__shfl_sync(0xffffffffu, om0, s), tt, lacc);
            }
            for (int s = r1 + 1; s <= r2; s++) {
                float2 ps = s_pb[s][lane];
                float m0 = fmaf(0.5f, ps.x, pr2x[0]);
                float m1 = fmaf(0.5f, ps.y, pr2y[0]);
                float tt = fmaf(m0, __log2f(m0), m1 * __log2f(m1));
                lacc = fmaf(__shfl_sync(0xffffffffu, om0, s), tt, lacc);
                m0 = fmaf(0.5f, ps.x, pr2x[1]);
                m1 = fmaf(0.5f, ps.y, pr2y[1]);
                tt = fmaf(m0, __log2f(m0), m1 * __log2f(m1));
                lacc = fmaf(__shfl_sync(0xffffffffu, om1, s), tt, lacc);
            }
            for (int s = r2 + 1; s <= r3; s++) {
                float2 ps = s_pb[s][lane];
                float m0 = fmaf(0.5f, ps.x, pr2x[0]);
                float m1 = fmaf(0.5f, ps.y, pr2y[0]);
                float tt = fmaf(m0, __log2f(m0), m1 * __log2f(m1));
                lacc = fmaf(__shfl_sync(0xffffffffu, om0, s), tt, lacc);
                m0 = fmaf(0.5f, ps.x, pr2x[1]);
                m1 = fmaf(0.5f, ps.y, pr2y[1]);
                tt = fmaf(m0, __log2f(m0), m1 * __log2f(m1));
                lacc = fmaf(__shfl_sync(0xffffffffu, om1, s), tt, lacc);
                m0 = fmaf(0.5f, ps.x, pr2x[2]);
                m1 = fmaf(0.5f, ps.y, pr2y[2]);
                tt = fmaf(m0, __log2f(m0), m1 * __log2f(m1));
                lacc = fmaf(__shfl_sync(0xffffffffu, om2, s), tt, lacc);
            }
            for (int s = r3 + 1; s < R_; s++) {
                float2 ps = s_pb[s][lane];
                float m0 = fmaf(0.5f, ps.x, pr2x[0]);
                float m1 = fmaf(0.5f, ps.y, pr2y[0]);
                float tt = fmaf(m0, __log2f(m0), m1 * __log2f(m1));
                lacc = fmaf(__shfl_sync(0xffffffffu, om0, s), tt, lacc);
                m0 = fmaf(0.5f, ps.x, pr2x[1]);
                m1 = fmaf(0.5f, ps.y, pr2y[1]);
                tt = fmaf(m0, __log2f(m0), m1 * __log2f(m1));
                lacc = fmaf(__shfl_sync(0xffffffffu, om1, s), tt, lacc);
                m0 = fmaf(0.5f, ps.x, pr2x[2]);
                m1 = fmaf(0.5f, ps.y, pr2y[2]);
                tt = fmaf(m0, __log2f(m0), m1 * __log2f(m1));
                lacc = fmaf(__shfl_sync(0xffffffffu, om2, s), tt, lacc);
                m0 = fmaf(0.5f, ps.x, pr2x[3]);
                m1 = fmaf(0.5f, ps.y, pr2y[3]);
                tt = fmaf(m0, __log2f(m0), m1 * __log2f(m1));
                lacc = fmaf(__shfl_sync(0xffffffffu, om3, s), tt, lacc);
            }
        }
    }

    // ---- final reduction + last-CTA writeout (log2 domain, scale once) ----
#pragma unroll
    for (int off = 16; off; off >>= 1)
        lacc += __shfl_xor_sync(0xffffffffu, lacc, off);
    if (lane == 0) s_red[wid] = fmaf(0.5f, eacc, -lacc) * LN2;
    __syncthreads();
    if (tid == 0) {
        float a = 0.f;
#pragma unroll
        for (int i = 0; i < 8; i++) a += s_red[i];
        atomicAdd(&g_acc, (double)a);
        __threadfence();
        unsigned int ticket = atomicAdd(&g_done, 1u);
        if (ticket == gridDim.x - 1) {
            double total = *(volatile double*)&g_acc;
            gout[0] = (float)(total / (496.0 + 1e-8));
        }
    }
}

extern "C" void kernel_launch(void* const* d_in, const int* in_sizes, int n_in,
                              void* d_out, int out_size) {
    const float* m = (const float*)d_in[0];
    const float* w = (const float*)d_in[1];
    const float* p = (const float*)d_in[2];
    const float* c = (const float*)d_in[3];
    float* out = (float*)d_out;
    (void)in_sizes; (void)n_in; (void)out_size;

    sheaf_setup_kernel<<<4, 256>>>(c);
    sheaf_kernel<<<GRID_, 256>>>(m, w, p, c, out);
}

// round 14
// speedup vs baseline: 2.1465x; 1.0451x over previous
#include <cuda_runtime.h>

// SheafLoss: B=4 T=1024 P=16 D=64 R=32 K=64, TAU=1
// d_in[0]=m (B,T,P,D) f32, d_in[1]=w (B,T,P) f32,
// d_in[2]=p (B,T,P,K) f32, d_in[3]=patch_centers (R,D) f32
// out: scalar f32

#define BT    4096
#define P_    16
#define D_    64
#define R_    32
#define K_    64
#define GRID_ 912          // 152 SMs x 6 CTAs: one persistent wave
#define LN2   0.6931471805599453f

typedef unsigned long long u64;

__device__ double g_acc;
__device__ unsigned int g_done;
__device__ float  g_omega[R_ * R_];
__device__ float  g_cn[R_];
__device__ float  g_hs[R_];     // hs[r] = sum_{s != r} omega[r][s]

__device__ __forceinline__ void cp_async16(unsigned saddr, const void* gaddr) {
    asm volatile("cp.async.ca.shared.global [%0], [%1], 16;" :: "r"(saddr), "l"(gaddr));
}
__device__ __forceinline__ void cp_commit() {
    asm volatile("cp.async.commit_group;");
}
__device__ __forceinline__ u64 pk2(float x, float y) {
    u64 r; asm("mov.b64 %0, {%1, %2};" : "=l"(r) : "f"(x), "f"(y)); return r;
}
__device__ __forceinline__ void upk2(u64 v, float& x, float& y) {
    asm("mov.b64 {%0, %1}, %2;" : "=f"(x), "=f"(y) : "l"(v));
}
__device__ __forceinline__ u64 add2(u64 a, u64 b) {
    u64 r; asm("add.rn.f32x2 %0, %1, %2;" : "=l"(r) : "l"(a), "l"(b)); return r;
}

// ---------------------------------------------------------------------------
// Setup: 4 blocks x 256 threads; block b handles rows [8b, 8b+8).
// ---------------------------------------------------------------------------
__global__ void __launch_bounds__(256) sheaf_setup_kernel(const float* __restrict__ gc) {
    __shared__ float sc[R_][D_ + 1];
    const int tid = threadIdx.x;
    for (int i = tid; i < R_ * D_; i += 256) sc[i >> 6][i & 63] = gc[i];
    __syncthreads();
    const int r = blockIdx.x * 8 + (tid >> 5);
    const int s = tid & 31;
    float cd = 0.f;
#pragma unroll 8
    for (int d = 0; d < D_; d++) {
        float df = sc[r][d] - sc[s][d];
        cd = fmaf(df, df, cd);
    }
    float omv = expf(-cd);
    g_omega[r * R_ + s] = omv;
    float hs = omv;
#pragma unroll
    for (int off = 16; off; off >>= 1)
        hs += __shfl_xor_sync(0xffffffffu, hs, off);
    if (s == 0) g_hs[r] = hs - 1.0f;
    float t = sc[r][s] * sc[r][s] + sc[r][s + 32] * sc[r][s + 32];
#pragma unroll
    for (int off = 16; off; off >>= 1)
        t += __shfl_xor_sync(0xffffffffu, t, off);
    if (s == 1) g_cn[r] = t;
    if (r == 0 && s == 2) { g_acc = 0.0; g_done = 0u; }
}

// ---------------------------------------------------------------------------
// Main: persistent grid (912 CTAs), grid-stride over tiles, 256 threads,
// 6 CTAs/SM, double-buffered m/p. Lane owns k-slice (2l, 2l+1); warp rows
// {w, 15-w, 16+w, 31-w}; omega register-resident via shfl.
// Algebra: s_pb holds p_bar + 1e-8. With q = pb'_r + pb'_s:
//   sum_k m*log2(m+eps) = 0.5*sum q*log2 q - 0.5*(S'_r + S'_s)
// so the pair loop accumulates om * sum q*log2 q per-lane, and rows carry
// hs_r * sum_lane pb'*(log2 pb' + 1)   (E-term + S-term, per-lane, no shfl).
// loss_tile(log2) = 0.5 * (eacc - lacc); convert by LN2 once.
// ---------------------------------------------------------------------------
__global__ void __launch_bounds__(256, 6) sheaf_kernel(
    const float* __restrict__ gm,
    const float* __restrict__ gw,
    const float* __restrict__ gp,
    const float* __restrict__ gc,
    float* __restrict__ gout)
{
    __shared__ float  s_c[R_][68];        // centers row-major, 16B rows
    __shared__ float4 s_m[2][256];        // double-buffered m tile
    __shared__ float4 s_p[2][256];        // double-buffered p tile
    __shared__ float  s_w[2][P_];
    __shared__ float  s_sm[P_][R_ + 1];
    __shared__ float2 s_pb[R_][R_];       // [r][lane] = (pb'[2l], pb'[2l+1])
    __shared__ float  s_cn[R_];
    __shared__ float  s_hs[R_];
    __shared__ float  s_red[8];

    const int tid  = threadIdx.x;
    const int lane = tid & 31;
    const int wid  = tid >> 5;

    const int r0 = wid, r1 = 15 - wid, r2 = 16 + wid, r3 = 31 - wid;

    // per-CTA constants (amortized over ~4.5 tiles)
    for (int i = tid; i < R_ * D_; i += 256) s_c[i >> 6][i & 63] = gc[i];
    if (tid < R_) { s_cn[tid] = g_cn[tid]; s_hs[tid] = g_hs[tid]; }

    // tile-invariant omega rows, register-resident
    const float om0 = g_omega[r0 * R_ + lane];
    const float om1 = g_omega[r1 * R_ + lane];
    const float om2 = g_omega[r2 * R_ + lane];
    const float om3 = g_omega[r3 * R_ + lane];

    // prologue: async-copy first tile into buffer 0
    {
        const int bt = blockIdx.x;
        unsigned a = (unsigned)__cvta_generic_to_shared(&s_m[0][tid]);
        unsigned b = (unsigned)__cvta_generic_to_shared(&s_p[0][tid]);
        cp_async16(a, (const float4*)(gm + (size_t)bt * 1024) + tid);
        cp_async16(b, (const float4*)(gp + (size_t)bt * 1024) + tid);
        cp_commit();
    }
    float pw = (tid < P_) ? gw[(size_t)blockIdx.x * P_ + tid] : 0.f;

    float lacc = 0.f;   // per-lane, log2 domain: sum om * q*log2 q
    float eacc = 0.f;   // per-lane, log2 domain: sum hs_r * pb'*(log2 pb' + 1)

    int it = 0;
#pragma unroll 1
    for (int bt = blockIdx.x; bt < BT; bt += GRID_, it++) {
        const int buf = it & 1;
        const int btn = bt + GRID_;
        if (btn < BT) {
            unsigned a = (unsigned)__cvta_generic_to_shared(&s_m[buf ^ 1][tid]);
            unsigned b = (unsigned)__cvta_generic_to_shared(&s_p[buf ^ 1][tid]);
            cp_async16(a, (const float4*)(gm + (size_t)btn * 1024) + tid);
            cp_async16(b, (const float4*)(gp + (size_t)btn * 1024) + tid);
            cp_commit();
            asm volatile("cp.async.wait_group 1;");
        } else {
            asm volatile("cp.async.wait_group 0;");
        }
        if (tid < P_) s_w[buf][tid] = pw;
        __syncthreads();   // buf visible; all warps done with previous pair loop
        if (btn < BT && tid < P_) pw = gw[(size_t)btn * P_ + tid];

        const float* smt = (const float*)s_m[buf];
        const float* spt = (const float*)s_p[buf];

        // ---- step 1: logits = 2*m.c - |c|^2; no max-sub (validated) ----
        {
            const int p0 = wid, p1 = wid + 8;
            const int r = lane;
            float a0 = 0.f, a1 = 0.f;
#pragma unroll
            for (int d = 0; d < D_; d += 4) {
                float4 cv  = *(const float4*)&s_c[r][d];
                float4 mv0 = *(const float4*)&smt[p0 * D_ + d];
                float4 mv1 = *(const float4*)&smt[p1 * D_ + d];
                a0 = fmaf(mv0.x, cv.x, fmaf(mv0.y, cv.y, fmaf(mv0.z, cv.z, fmaf(mv0.w, cv.w, a0))));
                a1 = fmaf(mv1.x, cv.x, fmaf(mv1.y, cv.y, fmaf(mv1.z, cv.z, fmaf(mv1.w, cv.w, a1))));
            }
            const float cn = s_cn[r];
            float e0 = __expf(fmaf(2.f, a0, -cn));
            float e1 = __expf(fmaf(2.f, a1, -cn));
            float sm0 = e0, sm1 = e1;
#pragma unroll
            for (int off = 16; off; off >>= 1) {
                sm0 += __shfl_xor_sync(0xffffffffu, sm0, off);
                sm1 += __shfl_xor_sync(0xffffffffu, sm1, off);
            }
            s_sm[p0][lane] = e0 * __fdividef(s_w[buf][p0], sm0);
            s_sm[p1][lane] = e1 * __fdividef(s_w[buf][p1], sm1);
        }
        __syncthreads();

        // ---- step 3: p_bar' + per-lane row terms; rows {r0..r3} ----
        u64 prq[4];
        {
            const int rows[4] = { r0, r1, r2, r3 };
            float acc0[4] = {0.f,0.f,0.f,0.f};
            float acc1[4] = {0.f,0.f,0.f,0.f};
#pragma unroll
            for (int pp = 0; pp < P_; pp++) {
                float2 sp = *(const float2*)&spt[pp * K_ + 2 * lane];
#pragma unroll
                for (int j = 0; j < 4; j++) {
                    float g = s_sm[pp][rows[j]];
                    acc0[j] = fmaf(sp.x, g, acc0[j]);
                    acc1[j] = fmaf(sp.y, g, acc1[j]);
                }
            }
#pragma unroll
            for (int j = 0; j < 4; j++) {
                const int r = rows[j];
                float v = (lane < P_) ? s_sm[lane][r] : 0.f;
#pragma unroll
                for (int off = 16; off; off >>= 1)
                    v += __shfl_xor_sync(0xffffffffu, v, off);
                float tm = __fdividef(1.0f, v + 1e-6f);
                float pb0 = fmaf(acc0[j], tm, 1e-8f);   // pb' = pb + eps
                float pb1 = fmaf(acc1[j], tm, 1e-8f);
                s_pb[r][lane] = make_float2(pb0, pb1);
                prq[j] = pk2(pb0, pb1);
                float l0 = __log2f(pb0) + 1.0f;
                float l1 = __log2f(pb1) + 1.0f;
                eacc = fmaf(s_hs[r], fmaf(pb0, l0, pb1 * l1), eacc);   // per-lane
            }
        }
        __syncthreads();

        // ---- pair loop: 4 rolled branch-free segments; q = pb'_r + pb'_s
        //      via one packed add; omega from registers via shfl. ----
        {
            for (int s = r0 + 1; s <= r1; s++) {
                u64 ps2 = *(const u64*)&s_pb[s][lane];
                float q0, q1; upk2(add2(prq[0], ps2), q0, q1);
                float tt = fmaf(q0, __log2f(q0), q1 * __log2f(q1));
                lacc = fmaf(__shfl_sync(0xffffffffu, om0, s), tt, lacc);
            }
            for (int s = r1 + 1; s <= r2; s++) {
                u64 ps2 = *(const u64*)&s_pb[s][lane];
                float q0, q1; upk2(add2(prq[0], ps2), q0, q1);
                float tt = fmaf(q0, __log2f(q0), q1 * __log2f(q1));
                lacc = fmaf(__shfl_sync(0xffffffffu, om0, s), tt, lacc);
                upk2(add2(prq[1], ps2), q0, q1);
                tt = fmaf(q0, __log2f(q0), q1 * __log2f(q1));
                lacc = fmaf(__shfl_sync(0xffffffffu, om1, s), tt, lacc);
            }
            for (int s = r2 + 1; s <= r3; s++) {
                u64 ps2 = *(const u64*)&s_pb[s][lane];
                float q0, q1; upk2(add2(prq[0], ps2), q0, q1);
                float tt = fmaf(q0, __log2f(q0), q1 * __log2f(q1));
                lacc = fmaf(__shfl_sync(0xffffffffu, om0, s), tt, lacc);
                upk2(add2(prq[1], ps2), q0, q1);
                tt = fmaf(q0, __log2f(q0), q1 * __log2f(q1));
                lacc = fmaf(__shfl_sync(0xffffffffu, om1, s), tt, lacc);
                upk2(add2(prq[2], ps2), q0, q1);
                tt = fmaf(q0, __log2f(q0), q1 * __log2f(q1));
                lacc = fmaf(__shfl_sync(0xffffffffu, om2, s), tt, lacc);
            }
            for (int s = r3 + 1; s < R_; s++) {
                u64 ps2 = *(const u64*)&s_pb[s][lane];
                float q0, q1; upk2(add2(prq[0], ps2), q0, q1);
                float tt = fmaf(q0, __log2f(q0), q1 * __log2f(q1));
                lacc = fmaf(__shfl_sync(0xffffffffu, om0, s), tt, lacc);
                upk2(add2(prq[1], ps2), q0, q1);
                tt = fmaf(q0, __log2f(q0), q1 * __log2f(q1));
                lacc = fmaf(__shfl_sync(0xffffffffu, om1, s), tt, lacc);
                upk2(add2(prq[2], ps2), q0, q1);
                tt = fmaf(q0, __log2f(q0), q1 * __log2f(q1));
                lacc = fmaf(__shfl_sync(0xffffffffu, om2, s), tt, lacc);
                upk2(add2(prq[3], ps2), q0, q1);
                tt = fmaf(q0, __log2f(q0), q1 * __log2f(q1));
                lacc = fmaf(__shfl_sync(0xffffffffu, om3, s), tt, lacc);
            }
        }
    }

    // ---- final reduction: loss(log2) = 0.5*(eacc - lacc), one butterfly ----
    float v = eacc - lacc;
#pragma unroll
    for (int off = 16; off; off >>= 1)
        v += __shfl_xor_sync(0xffffffffu, v, off);
    if (lane == 0) s_red[wid] = 0.5f * v * LN2;
    __syncthreads();
    if (tid == 0) {
        float a = 0.f;
#pragma unroll
        for (int i = 0; i < 8; i++) a += s_red[i];
        atomicAdd(&g_acc, (double)a);
        __threadfence();
        unsigned int ticket = atomicAdd(&g_done, 1u);
        if (ticket == gridDim.x - 1) {
            double total = *(volatile double*)&g_acc;
            gout[0] = (float)(total / (496.0 + 1e-8));
        }
    }
}

extern "C" void kernel_launch(void* const* d_in, const int* in_sizes, int n_in,
                              void* d_out, int out_size) {
    const float* m = (const float*)d_in[0];
    const float* w = (const float*)d_in[1];
    const float* p = (const float*)d_in[2];
    const float* c = (const float*)d_in[3];
    float* out = (float*)d_out;
    (void)in_sizes; (void)n_in; (void)out_size;

    sheaf_setup_kernel<<<4, 256>>>(c);
    sheaf_kernel<<<GRID_, 256>>>(m, w, p, c, out);
}